// round 9
// baseline (speedup 1.0000x reference)
#include <cuda_runtime.h>
#include <cuda_bf16.h>
#include <math.h>
#include <stdint.h>

// ---------------- problem constants ----------------
#define B_   64
#define L_   192
#define LT_  8
#define S_   200
#define C_   512
#define TD_  768
#define H_   8
#define D_   64
#define J_   22
#define M_   (B_ * L_)   // 12288

// ---------------- scratch ----------------
__device__ float g_ht [C_ * M_];        // depthwise output, K-major: [c][b*192+l]
__device__ float g_xa [B_ * S_ * C_];   // concat [cond(8) ; h(192)] per batch
__device__ float g_att[B_ * L_ * C_];
__device__ float g_z  [B_ * L_ * C_];
__device__ float g_h2 [B_ * L_ * C_];

__device__ __forceinline__ float silu_f(float v) { return v / (1.f + expf(-v)); }

__device__ __forceinline__ unsigned int f2tf32(float f) {
    unsigned int r;
    asm("cvt.rna.tf32.f32 %0, %1;" : "=r"(r) : "f"(f));
    return r;
}
__device__ __forceinline__ float rtf(float f) { return __uint_as_float(f2tf32(f)); }
__device__ __forceinline__ float4 cvt4(float4 v) {
    v.x = rtf(v.x); v.y = rtf(v.y); v.z = rtf(v.z); v.w = rtf(v.w);
    return v;
}
__device__ __forceinline__ void mma8(float* d, const unsigned int* a, const unsigned int* b) {
    asm volatile(
        "mma.sync.aligned.m16n8k8.row.col.f32.tf32.tf32.f32 "
        "{%0,%1,%2,%3}, {%4,%5,%6,%7}, {%8,%9}, {%0,%1,%2,%3};"
        : "+f"(d[0]), "+f"(d[1]), "+f"(d[2]), "+f"(d[3])
        : "r"(a[0]), "r"(a[1]), "r"(a[2]), "r"(a[3]), "r"(b[0]), "r"(b[1]));
}

// ================= kernel 1: depthwise conv + silu, K-major output =================
__global__ __launch_bounds__(192) void k_dw(const float* __restrict__ x,
                                            const float* __restrict__ dw_w,
                                            const float* __restrict__ dw_b,
                                            float* __restrict__ ht) {
    int c = blockIdx.x, b = blockIdx.y, l = threadIdx.x;
    __shared__ float w[J_];
    __shared__ float bias;
    if (threadIdx.x < J_) w[threadIdx.x] = dw_w[c * J_ + threadIdx.x];
    if (threadIdx.x == 0) bias = dw_b[c];
    __syncthreads();
    const float2* xp = (const float2*)(x + (((size_t)b * C_ + c) * L_ + l) * J_);
    float s = bias;
#pragma unroll
    for (int j = 0; j < J_ / 2; j++) {
        float2 v = xp[j];
        s += v.x * w[2 * j] + v.y * w[2 * j + 1];
    }
    ht[(size_t)c * M_ + b * L_ + l] = silu_f(s);
}

// ================= tf32 GEMM: double-buffered, register prefetch, 1 sync/tile ===
// Numerics identical to R7: fp32 gmem, cvt4 at smem staging.
#define BM 128
#define BN 128
#define BK 32
#define LDA_RM 36
#define LDA_KM 132
#define A_SZ 4608                 // floats; covers RM (128*36) and KM (32*132=4224)
#define STG_FL (2 * A_SZ)         // A + W per stage
#define SMEM_MM (2 * STG_FL * 4)  // 73728 bytes

template <int AKM, int ACT, int OMAP>
__global__ __launch_bounds__(256) void k_mm(const float* __restrict__ A,
                                            const float* __restrict__ W,
                                            const float* __restrict__ bias,
                                            float* __restrict__ out,
                                            int K, int lda) {
    extern __shared__ float smp[];

    const int tid = threadIdx.x;
    const int lane = tid & 31, wid = tid >> 5;
    const int warp_m = (wid & 1) * 64;
    const int warp_n = (wid >> 1) * 32;
    const int m0 = blockIdx.y * BM, n0 = blockIdx.x * BN;
    const int grow = tid >> 3, gcol = (tid & 7) * 4;
    const int kmc = (tid & 31) * 4, kkr = tid >> 5;
    const int c4 = lane & 3, r8 = lane >> 2;

    float acc[4][4][4];
#pragma unroll
    for (int i = 0; i < 4; i++)
#pragma unroll
        for (int j = 0; j < 4; j++)
#pragma unroll
            for (int r = 0; r < 4; r++) acc[i][j][r] = 0.f;

    float4 stA[4], stW[4];

    auto gload = [&](int kt) {
        if (AKM == 0) {
#pragma unroll
            for (int i = 0; i < 4; i++)
                stA[i] = *(const float4*)(A + (size_t)(m0 + grow + 32 * i) * lda + kt * BK + gcol);
        } else {
#pragma unroll
            for (int i = 0; i < 4; i++)
                stA[i] = *(const float4*)(A + (size_t)(kt * BK + kkr + 8 * i) * lda + m0 + kmc);
        }
#pragma unroll
        for (int i = 0; i < 4; i++)
            stW[i] = *(const float4*)(W + (size_t)(n0 + grow + 32 * i) * K + kt * BK + gcol);
    };
    auto sstore = [&](int s) {
        float* Ab = smp + s * STG_FL;
        float* Wb = Ab + A_SZ;
        if (AKM == 0) {
#pragma unroll
            for (int i = 0; i < 4; i++)
                *(float4*)&Ab[(grow + 32 * i) * LDA_RM + gcol] = cvt4(stA[i]);
        } else {
#pragma unroll
            for (int i = 0; i < 4; i++)
                *(float4*)&Ab[(kkr + 8 * i) * LDA_KM + kmc] = cvt4(stA[i]);
        }
#pragma unroll
        for (int i = 0; i < 4; i++)
            *(float4*)&Wb[(grow + 32 * i) * LDA_RM + gcol] = cvt4(stW[i]);
    };

    const int NT = K / BK;
    gload(0);
    sstore(0);
    __syncthreads();

    for (int kt = 0; kt < NT; kt++) {
        if (kt + 1 < NT) gload(kt + 1);  // long-latency LDGs overlap compute below

        const float* Ab = smp + (kt & 1) * STG_FL;
        const float* Wb = Ab + A_SZ;
#pragma unroll
        for (int ks = 0; ks < 4; ks++) {
            const int col = ks * 8 + c4;
            unsigned int afr[4][4], bfr[4][2];
#pragma unroll
            for (int mt = 0; mt < 4; mt++) {
                int row = warp_m + mt * 16 + r8;
                if (AKM == 0) {
                    afr[mt][0] = __float_as_uint(Ab[row * LDA_RM + col]);
                    afr[mt][1] = __float_as_uint(Ab[(row + 8) * LDA_RM + col]);
                    afr[mt][2] = __float_as_uint(Ab[row * LDA_RM + col + 4]);
                    afr[mt][3] = __float_as_uint(Ab[(row + 8) * LDA_RM + col + 4]);
                } else {
                    afr[mt][0] = __float_as_uint(Ab[col * LDA_KM + row]);
                    afr[mt][1] = __float_as_uint(Ab[col * LDA_KM + row + 8]);
                    afr[mt][2] = __float_as_uint(Ab[(col + 4) * LDA_KM + row]);
                    afr[mt][3] = __float_as_uint(Ab[(col + 4) * LDA_KM + row + 8]);
                }
            }
#pragma unroll
            for (int nt = 0; nt < 4; nt++) {
                int nrow = warp_n + nt * 8 + r8;
                bfr[nt][0] = __float_as_uint(Wb[nrow * LDA_RM + col]);
                bfr[nt][1] = __float_as_uint(Wb[nrow * LDA_RM + col + 4]);
            }
#pragma unroll
            for (int mt = 0; mt < 4; mt++)
#pragma unroll
                for (int nt = 0; nt < 4; nt++)
                    mma8(acc[mt][nt], afr[mt], bfr[nt]);
        }

        if (kt + 1 < NT) {
            sstore((kt + 1) & 1);  // writes buffer last read in iter kt-1 (safe)
            __syncthreads();
        }
    }

    // epilogue
#pragma unroll
    for (int nt = 0; nt < 4; nt++) {
        const int n = n0 + warp_n + nt * 8 + c4 * 2;
        const float bi0 = bias[n], bi1 = bias[n + 1];
#pragma unroll
        for (int mt = 0; mt < 4; mt++) {
            int m = m0 + warp_m + mt * 16 + r8;
#pragma unroll
            for (int half = 0; half < 2; half++) {
                int mm = m + half * 8;
                size_t orow;
                if (OMAP == 0) orow = (size_t)mm;
                else if (OMAP == 1) orow = (size_t)(mm >> 3) * S_ + (mm & 7);
                else orow = (size_t)(mm / L_) * S_ + LT_ + (mm % L_);
                float v0 = acc[mt][nt][half * 2 + 0] + bi0;
                float v1 = acc[mt][nt][half * 2 + 1] + bi1;
                if (ACT == 1) { v0 = silu_f(v0); v1 = silu_f(v1); }
                float2* op = (float2*)(out + orow * C_ + n);
                *op = make_float2(v0, v1);
            }
        }
    }
}

// ================= tensor-core attention (exact R7) =================
#define QLD 68
#define NJT 25

__global__ __launch_bounds__(192, 2) void k_attn_mma(const float* __restrict__ xa,
                                                     const float* __restrict__ rpe,
                                                     float* __restrict__ att) {
    extern __shared__ float sm[];
    float* Qs = sm;
    float* rp = sm + S_ * QLD;

    const int half = blockIdx.x, h = blockIdx.y, b = blockIdx.z;
    const int tid = threadIdx.x, lane = tid & 31, w = tid >> 5;
    const int r = lane >> 2, c = lane & 3;

    {
        const float* base = xa + (size_t)b * S_ * C_ + h * D_;
        int d = tid & 63;
        for (int s = tid >> 6; s < S_; s += 3)
            Qs[s * QLD + d] = rtf(base[(size_t)s * C_ + d]);
        for (int i = tid; i < 2 * S_ - 1; i += 192) rp[i] = rpe[h * (2 * S_ - 1) + i];
    }
    __syncthreads();

    const int i0 = LT_ + half * 96 + w * 16;
    const int i_lo = i0 + r, i_hi = i_lo + 8;

    unsigned int afr[8][4];
#pragma unroll
    for (int k = 0; k < 8; k++) {
        afr[k][0] = __float_as_uint(Qs[i_lo * QLD + k * 8 + c]);
        afr[k][1] = __float_as_uint(Qs[i_hi * QLD + k * 8 + c]);
        afr[k][2] = __float_as_uint(Qs[i_lo * QLD + k * 8 + c + 4]);
        afr[k][3] = __float_as_uint(Qs[i_hi * QLD + k * 8 + c + 4]);
    }
    float sc[NJT][4];
#pragma unroll
    for (int nt = 0; nt < NJT; nt++) {
        const int j0 = nt * 8;
        float acc[4] = {0.f, 0.f, 0.f, 0.f};
#pragma unroll
        for (int k = 0; k < 8; k++) {
            unsigned int bfr[2];
            bfr[0] = __float_as_uint(Qs[(j0 + r) * QLD + k * 8 + c]);
            bfr[1] = __float_as_uint(Qs[(j0 + r) * QLD + k * 8 + c + 4]);
            mma8(acc, afr[k], bfr);
        }
        const int j = j0 + 2 * c;
        sc[nt][0] = acc[0] * 0.125f + rp[j - i_lo + (S_ - 1)];
        sc[nt][1] = acc[1] * 0.125f + rp[j + 1 - i_lo + (S_ - 1)];
        sc[nt][2] = acc[2] * 0.125f + rp[j - i_hi + (S_ - 1)];
        sc[nt][3] = acc[3] * 0.125f + rp[j + 1 - i_hi + (S_ - 1)];
    }

    {
        float mx0 = -1e30f, mx1 = -1e30f;
#pragma unroll
        for (int nt = 0; nt < NJT; nt++) {
            mx0 = fmaxf(mx0, fmaxf(sc[nt][0], sc[nt][1]));
            mx1 = fmaxf(mx1, fmaxf(sc[nt][2], sc[nt][3]));
        }
        mx0 = fmaxf(mx0, __shfl_xor_sync(0xffffffffu, mx0, 1));
        mx0 = fmaxf(mx0, __shfl_xor_sync(0xffffffffu, mx0, 2));
        mx1 = fmaxf(mx1, __shfl_xor_sync(0xffffffffu, mx1, 1));
        mx1 = fmaxf(mx1, __shfl_xor_sync(0xffffffffu, mx1, 2));
        float s0 = 0.f, s1 = 0.f;
#pragma unroll
        for (int nt = 0; nt < NJT; nt++) {
            sc[nt][0] = __expf(sc[nt][0] - mx0);
            sc[nt][1] = __expf(sc[nt][1] - mx0);
            sc[nt][2] = __expf(sc[nt][2] - mx1);
            sc[nt][3] = __expf(sc[nt][3] - mx1);
            s0 += sc[nt][0] + sc[nt][1];
            s1 += sc[nt][2] + sc[nt][3];
        }
        s0 += __shfl_xor_sync(0xffffffffu, s0, 1);
        s0 += __shfl_xor_sync(0xffffffffu, s0, 2);
        s1 += __shfl_xor_sync(0xffffffffu, s1, 1);
        s1 += __shfl_xor_sync(0xffffffffu, s1, 2);
        const float inv0 = 1.f / s0, inv1 = 1.f / s1;
#pragma unroll
        for (int nt = 0; nt < NJT; nt++) {
            sc[nt][0] = rtf(sc[nt][0] * inv0);
            sc[nt][1] = rtf(sc[nt][1] * inv0);
            sc[nt][2] = rtf(sc[nt][2] * inv1);
            sc[nt][3] = rtf(sc[nt][3] * inv1);
        }
    }

    float acc[8][4];
#pragma unroll
    for (int nt = 0; nt < 8; nt++)
#pragma unroll
        for (int e = 0; e < 4; e++) acc[nt][e] = 0.f;

    const int L0 = (lane & ~3) | (c >> 1);
    const int L1 = L0 + 2;
    const bool odd = (c & 1);

#pragma unroll
    for (int kt = 0; kt < NJT; kt++) {
        float v00 = __shfl_sync(0xffffffffu, sc[kt][0], L0);
        float v01 = __shfl_sync(0xffffffffu, sc[kt][1], L0);
        float v10 = __shfl_sync(0xffffffffu, sc[kt][0], L1);
        float v11 = __shfl_sync(0xffffffffu, sc[kt][1], L1);
        float w00 = __shfl_sync(0xffffffffu, sc[kt][2], L0);
        float w01 = __shfl_sync(0xffffffffu, sc[kt][3], L0);
        float w10 = __shfl_sync(0xffffffffu, sc[kt][2], L1);
        float w11 = __shfl_sync(0xffffffffu, sc[kt][3], L1);
        unsigned int pa[4];
        pa[0] = __float_as_uint(odd ? v01 : v00);
        pa[1] = __float_as_uint(odd ? w01 : w00);
        pa[2] = __float_as_uint(odd ? v11 : v10);
        pa[3] = __float_as_uint(odd ? w11 : w10);
        const int kr0 = (kt * 8 + c) * QLD, kr1 = (kt * 8 + c + 4) * QLD;
#pragma unroll
        for (int nt = 0; nt < 8; nt++) {
            unsigned int bfr[2];
            bfr[0] = __float_as_uint(Qs[kr0 + nt * 8 + r]);
            bfr[1] = __float_as_uint(Qs[kr1 + nt * 8 + r]);
            mma8(acc[nt], pa, bfr);
        }
    }

    float* ob = att + ((size_t)b * L_ + (i0 - LT_)) * C_ + h * D_;
#pragma unroll
    for (int nt = 0; nt < 8; nt++) {
        const int dd = nt * 8 + 2 * c;
        *(float2*)&ob[(size_t)r * C_ + dd] = make_float2(acc[nt][0], acc[nt][1]);
        *(float2*)&ob[(size_t)(r + 8) * C_ + dd] = make_float2(acc[nt][2], acc[nt][3]);
    }
}

// ================= residual + layernorm (exact R7) =================
__device__ __forceinline__ float block_sum256(float v, float* red) {
    __syncthreads();
#pragma unroll
    for (int o = 16; o; o >>= 1) v += __shfl_xor_sync(0xffffffffu, v, o);
    int w = threadIdx.x >> 5;
    if ((threadIdx.x & 31) == 0) red[w] = v;
    __syncthreads();
    if (w == 0) {
        float x = ((threadIdx.x & 31) < 8) ? red[threadIdx.x & 31] : 0.f;
#pragma unroll
        for (int o = 4; o; o >>= 1) x += __shfl_xor_sync(0xffffffffu, x, o);
        if (threadIdx.x == 0) red[0] = x;
    }
    __syncthreads();
    return red[0];
}

__global__ __launch_bounds__(256) void k_ln(const float* __restrict__ z,
                                            const float* __restrict__ xa,
                                            const float* __restrict__ gamma,
                                            const float* __restrict__ beta,
                                            float* __restrict__ h2) {
    __shared__ float red[8];
    int m = blockIdx.x;
    int b = m / L_, l = m % L_;
    const float* zr = z + (size_t)m * C_;
    const float* rr = xa + ((size_t)b * S_ + LT_ + l) * C_;
    int t = threadIdx.x;
    float v0 = zr[t] + rr[t];
    float v1 = zr[t + 256] + rr[t + 256];
    float s = block_sum256(v0 + v1, red);
    float mu = s * (1.f / (float)C_);
    float d0 = v0 - mu, d1 = v1 - mu;
    float vs = block_sum256(d0 * d0 + d1 * d1, red);
    float rstd = rsqrtf(vs * (1.f / (float)C_) + 1e-5f);
    h2[(size_t)m * C_ + t] = d0 * rstd * gamma[t] + beta[t];
    h2[(size_t)m * C_ + t + 256] = d1 * rstd * gamma[t + 256] + beta[t + 256];
}

// ================= launch =================
extern "C" void kernel_launch(void* const* d_in, const int* in_sizes, int n_in,
                              void* d_out, int out_size) {
    const float* x         = (const float*)d_in[0];
    const float* text_emb1 = (const float*)d_in[2];
    const float* dw_w      = (const float*)d_in[6];
    const float* dw_b      = (const float*)d_in[7];
    const float* pw_w      = (const float*)d_in[8];
    const float* pw_b      = (const float*)d_in[9];
    const float* wt        = (const float*)d_in[10];
    const float* bt        = (const float*)d_in[11];
    const float* rpe       = (const float*)d_in[12];
    const float* w_out     = (const float*)d_in[13];
    const float* b_out     = (const float*)d_in[14];
    const float* ln_g      = (const float*)d_in[15];
    const float* ln_b      = (const float*)d_in[16];
    const float* wp        = (const float*)d_in[17];
    const float* bp        = (const float*)d_in[18];
    float* out = (float*)d_out;

    float *p_ht, *p_xa, *p_att, *p_z, *p_h2;
    cudaGetSymbolAddress((void**)&p_ht, g_ht);
    cudaGetSymbolAddress((void**)&p_xa, g_xa);
    cudaGetSymbolAddress((void**)&p_att, g_att);
    cudaGetSymbolAddress((void**)&p_z, g_z);
    cudaGetSymbolAddress((void**)&p_h2, g_h2);

    // 1. depthwise + silu -> g_ht (K-major)
    k_dw<<<dim3(C_, B_), 192>>>(x, dw_w, dw_b, p_ht);

    // smem opt-in for GEMMs (72KB dynamic)
    cudaFuncSetAttribute(k_mm<1, 0, 2>, cudaFuncAttributeMaxDynamicSharedMemorySize, SMEM_MM);
    cudaFuncSetAttribute(k_mm<0, 1, 1>, cudaFuncAttributeMaxDynamicSharedMemorySize, SMEM_MM);
    cudaFuncSetAttribute(k_mm<0, 0, 0>, cudaFuncAttributeMaxDynamicSharedMemorySize, SMEM_MM);
    cudaFuncSetAttribute(k_mm<0, 1, 0>, cudaFuncAttributeMaxDynamicSharedMemorySize, SMEM_MM);

    // 2. pointwise GEMM (A K-major) -> xa rows [8,200)
    k_mm<1, 0, 2><<<dim3(4, M_ / BM), 256, SMEM_MM>>>(p_ht, pw_w, pw_b, p_xa, C_, M_);

    // 3. cond GEMM + silu -> xa rows [0,8)
    k_mm<0, 1, 1><<<dim3(4, 4), 256, SMEM_MM>>>(text_emb1, wt, bt, p_xa, TD_, TD_);

    // 4. tensor-core attention
    int smem_a = (S_ * QLD + (2 * S_ - 1)) * sizeof(float);
    cudaFuncSetAttribute(k_attn_mma, cudaFuncAttributeMaxDynamicSharedMemorySize, smem_a);
    k_attn_mma<<<dim3(2, H_, B_), 192, smem_a>>>(p_xa, rpe, p_att);

    // 5. output projection
    k_mm<0, 0, 0><<<dim3(4, M_ / BM), 256, SMEM_MM>>>(p_att, w_out, b_out, p_z, C_, C_);

    // 6. residual + layernorm
    k_ln<<<B_ * L_, 256>>>(p_z, p_xa, ln_g, ln_b, p_h2);

    // 7. final projection + silu -> out
    k_mm<0, 1, 0><<<dim3(4, M_ / BM), 256, SMEM_MM>>>(p_h2, wp, bp, out, C_, C_);

    (void)in_sizes; (void)n_in; (void)out_size;
}

// round 12
// speedup vs baseline: 1.0188x; 1.0188x over previous
#include <cuda_runtime.h>
#include <cuda_bf16.h>
#include <math.h>
#include <stdint.h>

// ---------------- problem constants ----------------
#define B_   64
#define L_   192
#define LT_  8
#define S_   200
#define C_   512
#define TD_  768
#define H_   8
#define D_   64
#define J_   22
#define M_   (B_ * L_)   // 12288

// ---------------- scratch ----------------
__device__ float g_ht [C_ * M_];        // depthwise output, K-major: [c][b*192+l]
__device__ float g_xa [B_ * S_ * C_];   // concat [cond(8) ; h(192)] per batch
__device__ float g_att[B_ * L_ * C_];
__device__ float g_z  [B_ * L_ * C_];
__device__ float g_h2 [B_ * L_ * C_];

__device__ __forceinline__ float silu_f(float v) { return v / (1.f + expf(-v)); }

__device__ __forceinline__ unsigned int f2tf32(float f) {
    unsigned int r;
    asm("cvt.rna.tf32.f32 %0, %1;" : "=r"(r) : "f"(f));
    return r;
}
__device__ __forceinline__ float rtf(float f) { return __uint_as_float(f2tf32(f)); }
__device__ __forceinline__ float4 cvt4(float4 v) {
    v.x = rtf(v.x); v.y = rtf(v.y); v.z = rtf(v.z); v.w = rtf(v.w);
    return v;
}
__device__ __forceinline__ void mma8(float* d, const unsigned int* a, const unsigned int* b) {
    asm volatile(
        "mma.sync.aligned.m16n8k8.row.col.f32.tf32.tf32.f32 "
        "{%0,%1,%2,%3}, {%4,%5,%6,%7}, {%8,%9}, {%0,%1,%2,%3};"
        : "+f"(d[0]), "+f"(d[1]), "+f"(d[2]), "+f"(d[3])
        : "r"(a[0]), "r"(a[1]), "r"(a[2]), "r"(a[3]), "r"(b[0]), "r"(b[1]));
}

// ================= kernel 1: depthwise conv + silu, K-major output =================
__global__ __launch_bounds__(192) void k_dw(const float* __restrict__ x,
                                            const float* __restrict__ dw_w,
                                            const float* __restrict__ dw_b,
                                            float* __restrict__ ht) {
    int c = blockIdx.x, b = blockIdx.y, l = threadIdx.x;
    __shared__ float w[J_];
    __shared__ float bias;
    if (threadIdx.x < J_) w[threadIdx.x] = dw_w[c * J_ + threadIdx.x];
    if (threadIdx.x == 0) bias = dw_b[c];
    __syncthreads();
    const float2* xp = (const float2*)(x + (((size_t)b * C_ + c) * L_ + l) * J_);
    float s = bias;
#pragma unroll
    for (int j = 0; j < J_ / 2; j++) {
        float2 v = xp[j];
        s += v.x * w[2 * j] + v.y * w[2 * j + 1];
    }
    ht[(size_t)c * M_ + b * L_ + l] = silu_f(s);
}

// ================= tf32 GEMM: BM=128, BN=64, warp tile 32x32, 2-sync loop =========
// out[omap(m)][n] = act( sum_k A(m,k) * W[n][k] + bias[n] )
// AKM: 0 -> A row-major (M,K) lda=K ;  1 -> A K-major (K,M) lda=M
#define BM 128
#define BN 64
#define BK 32
#define LDA_RM 36
#define LDA_KM 132
#define LDB    36

template <int AKM, int ACT, int OMAP>
__global__ __launch_bounds__(256) void k_mm(const float* __restrict__ A,
                                            const float* __restrict__ W,
                                            const float* __restrict__ bias,
                                            float* __restrict__ out,
                                            int K, int lda) {
    __shared__ float As[BM * LDA_RM];   // covers RM(128*36) and KM(32*132)
    __shared__ float Ws[BN * LDB];      // 64*36

    const int tid = threadIdx.x;
    const int lane = tid & 31, wid = tid >> 5;
    const int warp_m = (wid & 3) * 32;   // 4 warps along M (tile 32)
    const int warp_n = (wid >> 2) * 32;  // 2 warps along N (tile 32)
    const int m0 = blockIdx.y * BM, n0 = blockIdx.x * BN;
    const int c4 = lane & 3, r8 = lane >> 2;

    float acc[2][4][4];
#pragma unroll
    for (int i = 0; i < 2; i++)
#pragma unroll
        for (int j = 0; j < 4; j++)
#pragma unroll
            for (int r = 0; r < 4; r++) acc[i][j][r] = 0.f;

    const int grow = tid >> 3, gcol = (tid & 7) * 4;
    const int kmc = (tid & 31) * 4, kkr = tid >> 5;

    float4 stA[4], stW[2];
    if (AKM == 0) {
#pragma unroll
        for (int i = 0; i < 4; i++)
            stA[i] = *(const float4*)(A + (size_t)(m0 + grow + 32 * i) * lda + gcol);
    } else {
#pragma unroll
        for (int i = 0; i < 4; i++)
            stA[i] = *(const float4*)(A + (size_t)(kkr + 8 * i) * lda + m0 + kmc);
    }
#pragma unroll
    for (int i = 0; i < 2; i++)
        stW[i] = *(const float4*)(W + (size_t)(n0 + grow + 32 * i) * K + gcol);

    for (int k0 = 0; k0 < K; k0 += BK) {
        __syncthreads();
        if (AKM == 0) {
#pragma unroll
            for (int i = 0; i < 4; i++)
                *(float4*)&As[(grow + 32 * i) * LDA_RM + gcol] = cvt4(stA[i]);
        } else {
#pragma unroll
            for (int i = 0; i < 4; i++)
                *(float4*)&As[(kkr + 8 * i) * LDA_KM + kmc] = cvt4(stA[i]);
        }
#pragma unroll
        for (int i = 0; i < 2; i++)
            *(float4*)&Ws[(grow + 32 * i) * LDB + gcol] = cvt4(stW[i]);
        __syncthreads();

        if (k0 + BK < K) {
            if (AKM == 0) {
#pragma unroll
                for (int i = 0; i < 4; i++)
                    stA[i] = *(const float4*)(A + (size_t)(m0 + grow + 32 * i) * lda + k0 + BK + gcol);
            } else {
#pragma unroll
                for (int i = 0; i < 4; i++)
                    stA[i] = *(const float4*)(A + (size_t)(k0 + BK + kkr + 8 * i) * lda + m0 + kmc);
            }
#pragma unroll
            for (int i = 0; i < 2; i++)
                stW[i] = *(const float4*)(W + (size_t)(n0 + grow + 32 * i) * K + k0 + BK + gcol);
        }

#pragma unroll
        for (int ks = 0; ks < 4; ks++) {
            const int col = ks * 8 + c4;
            unsigned int afr[2][4], bfr[4][2];
#pragma unroll
            for (int mt = 0; mt < 2; mt++) {
                int row = warp_m + mt * 16 + r8;
                if (AKM == 0) {
                    afr[mt][0] = __float_as_uint(As[row * LDA_RM + col]);
                    afr[mt][1] = __float_as_uint(As[(row + 8) * LDA_RM + col]);
                    afr[mt][2] = __float_as_uint(As[row * LDA_RM + col + 4]);
                    afr[mt][3] = __float_as_uint(As[(row + 8) * LDA_RM + col + 4]);
                } else {
                    afr[mt][0] = __float_as_uint(As[col * LDA_KM + row]);
                    afr[mt][1] = __float_as_uint(As[col * LDA_KM + row + 8]);
                    afr[mt][2] = __float_as_uint(As[(col + 4) * LDA_KM + row]);
                    afr[mt][3] = __float_as_uint(As[(col + 4) * LDA_KM + row + 8]);
                }
            }
#pragma unroll
            for (int nt = 0; nt < 4; nt++) {
                int nrow = warp_n + nt * 8 + r8;
                bfr[nt][0] = __float_as_uint(Ws[nrow * LDB + col]);
                bfr[nt][1] = __float_as_uint(Ws[nrow * LDB + col + 4]);
            }
#pragma unroll
            for (int mt = 0; mt < 2; mt++)
#pragma unroll
                for (int nt = 0; nt < 4; nt++)
                    mma8(acc[mt][nt], afr[mt], bfr[nt]);
        }
    }

    // epilogue
#pragma unroll
    for (int nt = 0; nt < 4; nt++) {
        const int n = n0 + warp_n + nt * 8 + c4 * 2;
        const float bi0 = bias[n], bi1 = bias[n + 1];
#pragma unroll
        for (int mt = 0; mt < 2; mt++) {
            int m = m0 + warp_m + mt * 16 + r8;
#pragma unroll
            for (int half = 0; half < 2; half++) {
                int mm = m + half * 8;
                size_t orow;
                if (OMAP == 0) orow = (size_t)mm;
                else if (OMAP == 1) orow = (size_t)(mm >> 3) * S_ + (mm & 7);
                else orow = (size_t)(mm / L_) * S_ + LT_ + (mm % L_);
                float v0 = acc[mt][nt][half * 2 + 0] + bi0;
                float v1 = acc[mt][nt][half * 2 + 1] + bi1;
                if (ACT == 1) { v0 = silu_f(v0); v1 = silu_f(v1); }
                float2* op = (float2*)(out + orow * C_ + n);
                *op = make_float2(v0, v1);
            }
        }
    }
}

// ================= tensor-core attention (exact R7) =================
#define QLD 68
#define NJT 25

__global__ __launch_bounds__(192, 2) void k_attn_mma(const float* __restrict__ xa,
                                                     const float* __restrict__ rpe,
                                                     float* __restrict__ att) {
    extern __shared__ float sm[];
    float* Qs = sm;
    float* rp = sm + S_ * QLD;

    const int half = blockIdx.x, h = blockIdx.y, b = blockIdx.z;
    const int tid = threadIdx.x, lane = tid & 31, w = tid >> 5;
    const int r = lane >> 2, c = lane & 3;

    {
        const float* base = xa + (size_t)b * S_ * C_ + h * D_;
        int d = tid & 63;
        for (int s = tid >> 6; s < S_; s += 3)
            Qs[s * QLD + d] = rtf(base[(size_t)s * C_ + d]);
        for (int i = tid; i < 2 * S_ - 1; i += 192) rp[i] = rpe[h * (2 * S_ - 1) + i];
    }
    __syncthreads();

    const int i0 = LT_ + half * 96 + w * 16;
    const int i_lo = i0 + r, i_hi = i_lo + 8;

    unsigned int afr[8][4];
#pragma unroll
    for (int k = 0; k < 8; k++) {
        afr[k][0] = __float_as_uint(Qs[i_lo * QLD + k * 8 + c]);
        afr[k][1] = __float_as_uint(Qs[i_hi * QLD + k * 8 + c]);
        afr[k][2] = __float_as_uint(Qs[i_lo * QLD + k * 8 + c + 4]);
        afr[k][3] = __float_as_uint(Qs[i_hi * QLD + k * 8 + c + 4]);
    }
    float sc[NJT][4];
#pragma unroll
    for (int nt = 0; nt < NJT; nt++) {
        const int j0 = nt * 8;
        float acc[4] = {0.f, 0.f, 0.f, 0.f};
#pragma unroll
        for (int k = 0; k < 8; k++) {
            unsigned int bfr[2];
            bfr[0] = __float_as_uint(Qs[(j0 + r) * QLD + k * 8 + c]);
            bfr[1] = __float_as_uint(Qs[(j0 + r) * QLD + k * 8 + c + 4]);
            mma8(acc, afr[k], bfr);
        }
        const int j = j0 + 2 * c;
        sc[nt][0] = acc[0] * 0.125f + rp[j - i_lo + (S_ - 1)];
        sc[nt][1] = acc[1] * 0.125f + rp[j + 1 - i_lo + (S_ - 1)];
        sc[nt][2] = acc[2] * 0.125f + rp[j - i_hi + (S_ - 1)];
        sc[nt][3] = acc[3] * 0.125f + rp[j + 1 - i_hi + (S_ - 1)];
    }

    {
        float mx0 = -1e30f, mx1 = -1e30f;
#pragma unroll
        for (int nt = 0; nt < NJT; nt++) {
            mx0 = fmaxf(mx0, fmaxf(sc[nt][0], sc[nt][1]));
            mx1 = fmaxf(mx1, fmaxf(sc[nt][2], sc[nt][3]));
        }
        mx0 = fmaxf(mx0, __shfl_xor_sync(0xffffffffu, mx0, 1));
        mx0 = fmaxf(mx0, __shfl_xor_sync(0xffffffffu, mx0, 2));
        mx1 = fmaxf(mx1, __shfl_xor_sync(0xffffffffu, mx1, 1));
        mx1 = fmaxf(mx1, __shfl_xor_sync(0xffffffffu, mx1, 2));
        float s0 = 0.f, s1 = 0.f;
#pragma unroll
        for (int nt = 0; nt < NJT; nt++) {
            sc[nt][0] = __expf(sc[nt][0] - mx0);
            sc[nt][1] = __expf(sc[nt][1] - mx0);
            sc[nt][2] = __expf(sc[nt][2] - mx1);
            sc[nt][3] = __expf(sc[nt][3] - mx1);
            s0 += sc[nt][0] + sc[nt][1];
            s1 += sc[nt][2] + sc[nt][3];
        }
        s0 += __shfl_xor_sync(0xffffffffu, s0, 1);
        s0 += __shfl_xor_sync(0xffffffffu, s0, 2);
        s1 += __shfl_xor_sync(0xffffffffu, s1, 1);
        s1 += __shfl_xor_sync(0xffffffffu, s1, 2);
        const float inv0 = 1.f / s0, inv1 = 1.f / s1;
#pragma unroll
        for (int nt = 0; nt < NJT; nt++) {
            sc[nt][0] = rtf(sc[nt][0] * inv0);
            sc[nt][1] = rtf(sc[nt][1] * inv0);
            sc[nt][2] = rtf(sc[nt][2] * inv1);
            sc[nt][3] = rtf(sc[nt][3] * inv1);
        }
    }

    float acc[8][4];
#pragma unroll
    for (int nt = 0; nt < 8; nt++)
#pragma unroll
        for (int e = 0; e < 4; e++) acc[nt][e] = 0.f;

    const int L0 = (lane & ~3) | (c >> 1);
    const int L1 = L0 + 2;
    const bool odd = (c & 1);

#pragma unroll
    for (int kt = 0; kt < NJT; kt++) {
        float v00 = __shfl_sync(0xffffffffu, sc[kt][0], L0);
        float v01 = __shfl_sync(0xffffffffu, sc[kt][1], L0);
        float v10 = __shfl_sync(0xffffffffu, sc[kt][0], L1);
        float v11 = __shfl_sync(0xffffffffu, sc[kt][1], L1);
        float w00 = __shfl_sync(0xffffffffu, sc[kt][2], L0);
        float w01 = __shfl_sync(0xffffffffu, sc[kt][3], L0);
        float w10 = __shfl_sync(0xffffffffu, sc[kt][2], L1);
        float w11 = __shfl_sync(0xffffffffu, sc[kt][3], L1);
        unsigned int pa[4];
        pa[0] = __float_as_uint(odd ? v01 : v00);
        pa[1] = __float_as_uint(odd ? w01 : w00);
        pa[2] = __float_as_uint(odd ? v11 : v10);
        pa[3] = __float_as_uint(odd ? w11 : w10);
        const int kr0 = (kt * 8 + c) * QLD, kr1 = (kt * 8 + c + 4) * QLD;
#pragma unroll
        for (int nt = 0; nt < 8; nt++) {
            unsigned int bfr[2];
            bfr[0] = __float_as_uint(Qs[kr0 + nt * 8 + r]);
            bfr[1] = __float_as_uint(Qs[kr1 + nt * 8 + r]);
            mma8(acc[nt], pa, bfr);
        }
    }

    float* ob = att + ((size_t)b * L_ + (i0 - LT_)) * C_ + h * D_;
#pragma unroll
    for (int nt = 0; nt < 8; nt++) {
        const int dd = nt * 8 + 2 * c;
        *(float2*)&ob[(size_t)r * C_ + dd] = make_float2(acc[nt][0], acc[nt][1]);
        *(float2*)&ob[(size_t)(r + 8) * C_ + dd] = make_float2(acc[nt][2], acc[nt][3]);
    }
}

// ================= residual + layernorm (exact R7) =================
__device__ __forceinline__ float block_sum256(float v, float* red) {
    __syncthreads();
#pragma unroll
    for (int o = 16; o; o >>= 1) v += __shfl_xor_sync(0xffffffffu, v, o);
    int w = threadIdx.x >> 5;
    if ((threadIdx.x & 31) == 0) red[w] = v;
    __syncthreads();
    if (w == 0) {
        float x = ((threadIdx.x & 31) < 8) ? red[threadIdx.x & 31] : 0.f;
#pragma unroll
        for (int o = 4; o; o >>= 1) x += __shfl_xor_sync(0xffffffffu, x, o);
        if (threadIdx.x == 0) red[0] = x;
    }
    __syncthreads();
    return red[0];
}

__global__ __launch_bounds__(256) void k_ln(const float* __restrict__ z,
                                            const float* __restrict__ xa,
                                            const float* __restrict__ gamma,
                                            const float* __restrict__ beta,
                                            float* __restrict__ h2) {
    __shared__ float red[8];
    int m = blockIdx.x;
    int b = m / L_, l = m % L_;
    const float* zr = z + (size_t)m * C_;
    const float* rr = xa + ((size_t)b * S_ + LT_ + l) * C_;
    int t = threadIdx.x;
    float v0 = zr[t] + rr[t];
    float v1 = zr[t + 256] + rr[t + 256];
    float s = block_sum256(v0 + v1, red);
    float mu = s * (1.f / (float)C_);
    float d0 = v0 - mu, d1 = v1 - mu;
    float vs = block_sum256(d0 * d0 + d1 * d1, red);
    float rstd = rsqrtf(vs * (1.f / (float)C_) + 1e-5f);
    h2[(size_t)m * C_ + t] = d0 * rstd * gamma[t] + beta[t];
    h2[(size_t)m * C_ + t + 256] = d1 * rstd * gamma[t + 256] + beta[t + 256];
}

// ================= launch =================
extern "C" void kernel_launch(void* const* d_in, const int* in_sizes, int n_in,
                              void* d_out, int out_size) {
    const float* x         = (const float*)d_in[0];
    const float* text_emb1 = (const float*)d_in[2];
    const float* dw_w      = (const float*)d_in[6];
    const float* dw_b      = (const float*)d_in[7];
    const float* pw_w      = (const float*)d_in[8];
    const float* pw_b      = (const float*)d_in[9];
    const float* wt        = (const float*)d_in[10];
    const float* bt        = (const float*)d_in[11];
    const float* rpe       = (const float*)d_in[12];
    const float* w_out     = (const float*)d_in[13];
    const float* b_out     = (const float*)d_in[14];
    const float* ln_g      = (const float*)d_in[15];
    const float* ln_b      = (const float*)d_in[16];
    const float* wp        = (const float*)d_in[17];
    const float* bp        = (const float*)d_in[18];
    float* out = (float*)d_out;

    float *p_ht, *p_xa, *p_att, *p_z, *p_h2;
    cudaGetSymbolAddress((void**)&p_ht, g_ht);
    cudaGetSymbolAddress((void**)&p_xa, g_xa);
    cudaGetSymbolAddress((void**)&p_att, g_att);
    cudaGetSymbolAddress((void**)&p_z, g_z);
    cudaGetSymbolAddress((void**)&p_h2, g_h2);

    // 1. depthwise + silu -> g_ht (K-major)
    k_dw<<<dim3(C_, B_), 192>>>(x, dw_w, dw_b, p_ht);

    // 2. pointwise GEMM (A K-major) -> xa rows [8,200)
    k_mm<1, 0, 2><<<dim3(C_ / BN, M_ / BM), 256>>>(p_ht, pw_w, pw_b, p_xa, C_, M_);

    // 3. cond GEMM + silu -> xa rows [0,8)
    k_mm<0, 1, 1><<<dim3(C_ / BN, 4), 256>>>(text_emb1, wt, bt, p_xa, TD_, TD_);

    // 4. tensor-core attention
    int smem_a = (S_ * QLD + (2 * S_ - 1)) * sizeof(float);
    cudaFuncSetAttribute(k_attn_mma, cudaFuncAttributeMaxDynamicSharedMemorySize, smem_a);
    k_attn_mma<<<dim3(2, H_, B_), 192, smem_a>>>(p_xa, rpe, p_att);

    // 5. output projection
    k_mm<0, 0, 0><<<dim3(C_ / BN, M_ / BM), 256>>>(p_att, w_out, b_out, p_z, C_, C_);

    // 6. residual + layernorm
    k_ln<<<B_ * L_, 256>>>(p_z, p_xa, ln_g, ln_b, p_h2);

    // 7. final projection + silu -> out
    k_mm<0, 1, 0><<<dim3(C_ / BN, M_ / BM), 256>>>(p_h2, wp, bp, out, C_, C_);

    (void)in_sizes; (void)n_in; (void)out_size;
}